// round 4
// baseline (speedup 1.0000x reference)
#include <cuda_runtime.h>
#include <math.h>
#include <stdint.h>

#define QLEN 1024
#define MLEN 1024
#define BSZ 4
#define DMODEL 512
#define NH 8
#define DHEAD 64
#define DFF 2048
#define NLAYER 3
#define KLEN (QLEN + MLEN)
#define MROWS (QLEN * BSZ)   /* 4096 */
#define CROWS (KLEN * BSZ)   /* 8192 */

// ---------------- scratch (device globals; no allocation allowed) -------------
static __device__ float g_h[MROWS * DMODEL];        // 8 MB
static __device__ float g_c[CROWS * DMODEL];        // 16 MB
static __device__ float g_q[MROWS * DMODEL];        // 8 MB
static __device__ float g_kv[CROWS * 2 * DMODEL];   // 32 MB
static __device__ float g_vec[MROWS * DMODEL];      // 8 MB
static __device__ float g_ff[MROWS * DFF];          // 32 MB
static __device__ float g_tmp[MROWS * DMODEL];      // 8 MB

// ---------------- embedding + sinusoidal position -----------------------------
__global__ void embed_kernel(const int* __restrict__ inp,
                             const float* __restrict__ emb,
                             float* __restrict__ h) {
    int idx = blockIdx.x * blockDim.x + threadIdx.x;
    if (idx >= MROWS * DMODEL) return;
    int d   = idx & (DMODEL - 1);
    int row = idx >> 9;          // i*BSZ + b
    int i   = row >> 2;          // BSZ = 4
    int tok = inp[row];
    float val = emb[(size_t)tok * DMODEL + d] * 22.62741699796952f; // sqrt(512)
    float pos = (float)(QLEN - 1 - i);
    int j = (d < DMODEL / 2) ? d : d - DMODEL / 2;
    float f = powf(10000.0f, -(float)j * (1.0f / 256.0f));
    float ang = pos * f;
    val += (d < DMODEL / 2) ? sinf(ang) : cosf(ang);
    h[idx] = val;
}

// ---------------- concat: c = [mems[l]; h] along rows -------------------------
__global__ void concat_kernel(const float* __restrict__ mems_l,
                              const float* __restrict__ h,
                              float* __restrict__ c) {
    const int nhalf = MROWS * DMODEL / 4;
    int idx = blockIdx.x * blockDim.x + threadIdx.x;
    if (idx >= 2 * nhalf) return;
    float4 v = (idx < nhalf) ? ((const float4*)mems_l)[idx]
                             : ((const float4*)h)[idx - nhalf];
    ((float4*)c)[idx] = v;
}

// ---------------- TF32 tensor-core GEMM: 128x128x16, mma.m16n8k8 --------------
// C[M,N] = A[M,K] @ B[K,N] (+ epilogue)
// EPI: 0 = none, 1 = relu(x + bias), 2 = x + res, 3 = x + bias + res
__device__ __forceinline__ uint32_t f2tf(float x) {
    uint32_t r;
    asm("cvt.rna.tf32.f32 %0, %1;" : "=r"(r) : "f"(x));
    return r;
}

template <int EPI>
__global__ __launch_bounds__(256)
void gemm_tf32_kernel(const float* __restrict__ A, const float* __restrict__ B,
                      float* __restrict__ C, int M, int N, int K,
                      const float* __restrict__ bias, const float* __restrict__ res) {
    // As[m][k]: stride 20 -> fragment loads conflict-free; 16B-aligned rows
    // Bs[k][n]: stride 136 -> fragment loads conflict-free; 16B-aligned rows
    __shared__ __align__(16) uint32_t As[2][128][20];
    __shared__ __align__(16) uint32_t Bs[2][16][136];

    const int t    = threadIdx.x;
    const int lane = t & 31;
    const int warp = t >> 5;
    const int wm   = warp & 3;          // 0..3 -> m offset wm*32
    const int wn   = warp >> 2;         // 0..1 -> n offset wn*64
    const int lr   = lane >> 2;         // 0..7
    const int lc   = lane & 3;          // 0..3
    const int bm   = blockIdx.y * 128, bn = blockIdx.x * 128;
    const int m0   = wm * 32, n0 = wn * 64;

    // gmem->smem mapping (2 float4 per thread per operand per chunk)
    const int amA = t >> 2;             // A row for idx t (0..63), +64 for t+256
    const int akA = (t & 3) * 4;        // A k offset (0,4,8,12)
    const int bkB = t >> 5;             // B row for idx t (0..7), +8 for t+256
    const int bnB = (t & 31) * 4;       // B col (0..124)

    const float* Aptr = A + (size_t)(bm + amA) * K + akA;
    const float* Bptr = B + (size_t)bkB * N + bn + bnB;
    const size_t Astep64 = (size_t)64 * K;
    const size_t Bstep8  = (size_t)8 * N;

    float acc[2][8][4];
#pragma unroll
    for (int i = 0; i < 2; i++)
#pragma unroll
        for (int j = 0; j < 8; j++)
#pragma unroll
            for (int r = 0; r < 4; r++) acc[i][j][r] = 0.0f;

    float4 aR0 = *(const float4*)Aptr;
    float4 aR1 = *(const float4*)(Aptr + Astep64);
    float4 bR0 = *(const float4*)Bptr;
    float4 bR1 = *(const float4*)(Bptr + Bstep8);

    int buf = 0;
    As[0][amA][akA + 0]      = f2tf(aR0.x); As[0][amA][akA + 1]      = f2tf(aR0.y);
    As[0][amA][akA + 2]      = f2tf(aR0.z); As[0][amA][akA + 3]      = f2tf(aR0.w);
    As[0][amA + 64][akA + 0] = f2tf(aR1.x); As[0][amA + 64][akA + 1] = f2tf(aR1.y);
    As[0][amA + 64][akA + 2] = f2tf(aR1.z); As[0][amA + 64][akA + 3] = f2tf(aR1.w);
    Bs[0][bkB][bnB + 0]     = f2tf(bR0.x); Bs[0][bkB][bnB + 1]     = f2tf(bR0.y);
    Bs[0][bkB][bnB + 2]     = f2tf(bR0.z); Bs[0][bkB][bnB + 3]     = f2tf(bR0.w);
    Bs[0][bkB + 8][bnB + 0] = f2tf(bR1.x); Bs[0][bkB + 8][bnB + 1] = f2tf(bR1.y);
    Bs[0][bkB + 8][bnB + 2] = f2tf(bR1.z); Bs[0][bkB + 8][bnB + 3] = f2tf(bR1.w);
    __syncthreads();

    const int KB = K >> 4;
    for (int kb = 0; kb < KB; kb++) {
        if (kb + 1 < KB) {
            const float* Ap = Aptr + (kb + 1) * 16;
            const float* Bp = Bptr + (size_t)(kb + 1) * 16 * N;
            aR0 = *(const float4*)Ap;
            aR1 = *(const float4*)(Ap + Astep64);
            bR0 = *(const float4*)Bp;
            bR1 = *(const float4*)(Bp + Bstep8);
        }
#pragma unroll
        for (int ks = 0; ks < 2; ks++) {
            const int k0 = ks * 8;
            uint32_t af[2][4];
#pragma unroll
            for (int mt = 0; mt < 2; mt++) {
                int mr = m0 + mt * 16 + lr;
                af[mt][0] = As[buf][mr][k0 + lc];
                af[mt][1] = As[buf][mr + 8][k0 + lc];
                af[mt][2] = As[buf][mr][k0 + lc + 4];
                af[mt][3] = As[buf][mr + 8][k0 + lc + 4];
            }
            uint32_t bf[8][2];
#pragma unroll
            for (int nt = 0; nt < 8; nt++) {
                int nc = n0 + nt * 8 + lr;
                bf[nt][0] = Bs[buf][k0 + lc][nc];
                bf[nt][1] = Bs[buf][k0 + lc + 4][nc];
            }
#pragma unroll
            for (int mt = 0; mt < 2; mt++)
#pragma unroll
                for (int nt = 0; nt < 8; nt++) {
                    asm volatile(
                        "mma.sync.aligned.m16n8k8.row.col.f32.tf32.tf32.f32 "
                        "{%0,%1,%2,%3}, {%4,%5,%6,%7}, {%8,%9}, {%0,%1,%2,%3};"
                        : "+f"(acc[mt][nt][0]), "+f"(acc[mt][nt][1]),
                          "+f"(acc[mt][nt][2]), "+f"(acc[mt][nt][3])
                        : "r"(af[mt][0]), "r"(af[mt][1]), "r"(af[mt][2]), "r"(af[mt][3]),
                          "r"(bf[nt][0]), "r"(bf[nt][1]));
                }
        }
        if (kb + 1 < KB) {
            buf ^= 1;
            As[buf][amA][akA + 0]      = f2tf(aR0.x); As[buf][amA][akA + 1]      = f2tf(aR0.y);
            As[buf][amA][akA + 2]      = f2tf(aR0.z); As[buf][amA][akA + 3]      = f2tf(aR0.w);
            As[buf][amA + 64][akA + 0] = f2tf(aR1.x); As[buf][amA + 64][akA + 1] = f2tf(aR1.y);
            As[buf][amA + 64][akA + 2] = f2tf(aR1.z); As[buf][amA + 64][akA + 3] = f2tf(aR1.w);
            Bs[buf][bkB][bnB + 0]     = f2tf(bR0.x); Bs[buf][bkB][bnB + 1]     = f2tf(bR0.y);
            Bs[buf][bkB][bnB + 2]     = f2tf(bR0.z); Bs[buf][bkB][bnB + 3]     = f2tf(bR0.w);
            Bs[buf][bkB + 8][bnB + 0] = f2tf(bR1.x); Bs[buf][bkB + 8][bnB + 1] = f2tf(bR1.y);
            Bs[buf][bkB + 8][bnB + 2] = f2tf(bR1.z); Bs[buf][bkB + 8][bnB + 3] = f2tf(bR1.w);
        }
        __syncthreads();
    }

    // epilogue: each mma tile writes float2 pairs (c0,c1) and (c2,c3)
#pragma unroll
    for (int mt = 0; mt < 2; mt++) {
#pragma unroll
        for (int half = 0; half < 2; half++) {
            int row = bm + m0 + mt * 16 + lr + half * 8;
            float* Crow = C + (size_t)row * N + bn;
            const float* Rrow = (EPI >= 2) ? (res + (size_t)row * N + bn) : nullptr;
#pragma unroll
            for (int nt = 0; nt < 8; nt++) {
                int col = n0 + nt * 8 + lc * 2;
                float2 v = make_float2(acc[mt][nt][half * 2], acc[mt][nt][half * 2 + 1]);
                if (EPI == 1 || EPI == 3) {
                    float2 bb = *(const float2*)(bias + bn + col);
                    v.x += bb.x; v.y += bb.y;
                }
                if (EPI == 1) { v.x = fmaxf(v.x, 0.f); v.y = fmaxf(v.y, 0.f); }
                if (EPI >= 2) {
                    float2 rr = *(const float2*)(Rrow + col);
                    v.x += rr.x; v.y += rr.y;
                }
                *(float2*)&Crow[col] = v;
            }
        }
    }
}

// ---------------- flash attention (online softmax), fp32 ----------------------
__global__ __launch_bounds__(256)
void attn_kernel(const float* __restrict__ Q, const float* __restrict__ KV,
                 float* __restrict__ Vout) {
    __shared__ float Qs[64][65];
    __shared__ float Ks[32][65];
    __shared__ float Vs[32][65];
    __shared__ float Ss[64][33];
    __shared__ float m_s[64], l_s[64], al_s[64];

    const int qb = blockIdx.x, b = blockIdx.y, hh = blockIdx.z;
    const int t = threadIdx.x;

    for (int idx = t; idx < 64 * 64; idx += 256) {
        int qi = idx >> 6, d = idx & 63;
        Qs[qi][d] = Q[((size_t)((qb * 64 + qi) * BSZ + b)) * DMODEL + hh * DHEAD + d];
    }
    if (t < 64) { m_s[t] = -INFINITY; l_s[t] = 0.0f; }

    float acc[4][4] = {};
    const int tys = t >> 3, txs = t & 7;
    const int tyd = t >> 4, txd = t & 15;
    const int srow = t >> 2, sq = t & 3;

    const int nTiles    = 34 + 2 * qb;
    const int firstMask = 32 + 2 * qb;

    for (int tile = 0; tile < nTiles; tile++) {
        const int j0 = tile * 32;
        __syncthreads();
        for (int idx = t; idx < 32 * 64; idx += 256) {
            int kj = idx >> 6, d = idx & 63;
            size_t base = ((size_t)(j0 + kj) * BSZ + b) * (2 * DMODEL) + hh * DHEAD + d;
            Ks[kj][d] = KV[base];
            Vs[kj][d] = KV[base + DMODEL];
        }
        __syncthreads();

        float s0[4] = {}, s1[4] = {};
#pragma unroll 16
        for (int d = 0; d < 64; d++) {
            float q0 = Qs[2 * tys][d], q1 = Qs[2 * tys + 1][d];
#pragma unroll
            for (int j = 0; j < 4; j++) {
                float kvv = Ks[4 * txs + j][d];
                s0[j] = fmaf(q0, kvv, s0[j]);
                s1[j] = fmaf(q1, kvv, s1[j]);
            }
        }
        const bool maskTile = (tile >= firstMask);
#pragma unroll
        for (int j = 0; j < 4; j++) {
            float v0 = s0[j] * 0.125f, v1 = s1[j] * 0.125f;
            if (maskTile) {
                int key = j0 + 4 * txs + j;
                if (key > MLEN + qb * 64 + 2 * tys)     v0 = -INFINITY;
                if (key > MLEN + qb * 64 + 2 * tys + 1) v1 = -INFINITY;
            }
            Ss[2 * tys][4 * txs + j]     = v0;
            Ss[2 * tys + 1][4 * txs + j] = v1;
        }
        __syncthreads();

        float sv[8];
        float mx = -INFINITY;
#pragma unroll
        for (int j = 0; j < 8; j++) { sv[j] = Ss[srow][sq * 8 + j]; mx = fmaxf(mx, sv[j]); }
        mx = fmaxf(mx, __shfl_xor_sync(0xffffffffu, mx, 1));
        mx = fmaxf(mx, __shfl_xor_sync(0xffffffffu, mx, 2));
        float mOld = m_s[srow];
        float mNew = fmaxf(mOld, mx);
        float al   = expf(mOld - mNew);
        float sum = 0.0f;
#pragma unroll
        for (int j = 0; j < 8; j++) {
            float p = expf(sv[j] - mNew);
            Ss[srow][sq * 8 + j] = p;
            sum += p;
        }
        sum += __shfl_xor_sync(0xffffffffu, sum, 1);
        sum += __shfl_xor_sync(0xffffffffu, sum, 2);
        if (sq == 0) { m_s[srow] = mNew; l_s[srow] = l_s[srow] * al + sum; al_s[srow] = al; }
        __syncthreads();

#pragma unroll
        for (int r = 0; r < 4; r++) {
            float a = al_s[4 * tyd + r];
#pragma unroll
            for (int j = 0; j < 4; j++) acc[r][j] *= a;
        }
#pragma unroll 8
        for (int kj = 0; kj < 32; kj++) {
            float p[4], vv[4];
#pragma unroll
            for (int r = 0; r < 4; r++) p[r] = Ss[4 * tyd + r][kj];
#pragma unroll
            for (int j = 0; j < 4; j++) vv[j] = Vs[kj][4 * txd + j];
#pragma unroll
            for (int r = 0; r < 4; r++)
#pragma unroll
                for (int j = 0; j < 4; j++)
                    acc[r][j] = fmaf(p[r], vv[j], acc[r][j]);
        }
    }
    __syncthreads();

#pragma unroll
    for (int r = 0; r < 4; r++) {
        int qi = 4 * tyd + r;
        float inv_l = 1.0f / l_s[qi];
#pragma unroll
        for (int j = 0; j < 4; j++) {
            Vout[((size_t)((qb * 64 + qi) * BSZ + b)) * DMODEL + hh * DHEAD + 4 * txd + j] =
                acc[r][j] * inv_l;
        }
    }
}

// ---------------- layernorm over last dim (512), biased variance -------------
__global__ __launch_bounds__(128)
void ln_kernel(const float* __restrict__ x, const float* __restrict__ g,
               const float* __restrict__ bparm, float* __restrict__ out) {
    const int row = blockIdx.x;
    const int t = threadIdx.x;
    float4 v = ((const float4*)(x + (size_t)row * DMODEL))[t];
    float s  = v.x + v.y + v.z + v.w;
    float s2 = fmaf(v.x, v.x, fmaf(v.y, v.y, fmaf(v.z, v.z, v.w * v.w)));
#pragma unroll
    for (int o = 16; o > 0; o >>= 1) {
        s  += __shfl_down_sync(0xffffffffu, s, o);
        s2 += __shfl_down_sync(0xffffffffu, s2, o);
    }
    __shared__ float ss[4], ss2[4];
    int w = t >> 5;
    if ((t & 31) == 0) { ss[w] = s; ss2[w] = s2; }
    __syncthreads();
    float tot  = ss[0] + ss[1] + ss[2] + ss[3];
    float tot2 = ss2[0] + ss2[1] + ss2[2] + ss2[3];
    float mu  = tot * (1.0f / DMODEL);
    float var = tot2 * (1.0f / DMODEL) - mu * mu;
    float rs  = rsqrtf(var + 1e-5f);
    float4 gg = ((const float4*)g)[t];
    float4 bb = ((const float4*)bparm)[t];
    float4 o;
    o.x = (v.x - mu) * rs * gg.x + bb.x;
    o.y = (v.y - mu) * rs * gg.y + bb.y;
    o.z = (v.z - mu) * rs * gg.z + bb.z;
    o.w = (v.w - mu) * rs * gg.w + bb.w;
    ((float4*)(out + (size_t)row * DMODEL))[t] = o;
}

// ---------------- launch ------------------------------------------------------
extern "C" void kernel_launch(void* const* d_in, const int* in_sizes, int n_in,
                              void* d_out, int out_size) {
    const int*   inp  = (const int*)d_in[0];
    const float* emb  = (const float*)d_in[1];
    const float* mems = (const float*)d_in[2];
    const float* Wq   = (const float*)d_in[3];
    const float* Wkv  = (const float*)d_in[4];
    const float* Wo   = (const float*)d_in[5];
    const float* ln1g = (const float*)d_in[6];
    const float* ln1b = (const float*)d_in[7];
    const float* W1   = (const float*)d_in[8];
    const float* b1   = (const float*)d_in[9];
    const float* W2   = (const float*)d_in[10];
    const float* b2   = (const float*)d_in[11];
    const float* ln2g = (const float*)d_in[12];
    const float* ln2b = (const float*)d_in[13];
    float* out = (float*)d_out;

    float *h, *c, *q, *kv, *vec, *ff, *tmp;
    cudaGetSymbolAddress((void**)&h,   g_h);
    cudaGetSymbolAddress((void**)&c,   g_c);
    cudaGetSymbolAddress((void**)&q,   g_q);
    cudaGetSymbolAddress((void**)&kv,  g_kv);
    cudaGetSymbolAddress((void**)&vec, g_vec);
    cudaGetSymbolAddress((void**)&ff,  g_ff);
    cudaGetSymbolAddress((void**)&tmp, g_tmp);

    embed_kernel<<<(MROWS * DMODEL + 255) / 256, 256>>>(inp, emb, h);

    for (int l = 0; l < NLAYER; l++) {
        concat_kernel<<<(CROWS * DMODEL / 4 + 255) / 256, 256>>>(
            mems + (size_t)l * MLEN * BSZ * DMODEL, h, c);

        gemm_tf32_kernel<0><<<dim3(DMODEL / 128, MROWS / 128), 256>>>(
            h, Wq + (size_t)l * DMODEL * DMODEL, q,
            MROWS, DMODEL, DMODEL, nullptr, nullptr);

        gemm_tf32_kernel<0><<<dim3(2 * DMODEL / 128, CROWS / 128), 256>>>(
            c, Wkv + (size_t)l * DMODEL * 2 * DMODEL, kv,
            CROWS, 2 * DMODEL, DMODEL, nullptr, nullptr);

        attn_kernel<<<dim3(QLEN / 64, BSZ, NH), 256>>>(q, kv, vec);

        gemm_tf32_kernel<2><<<dim3(DMODEL / 128, MROWS / 128), 256>>>(
            vec, Wo + (size_t)l * DMODEL * DMODEL, tmp,
            MROWS, DMODEL, DMODEL, nullptr, h);

        ln_kernel<<<MROWS, 128>>>(tmp, ln1g + l * DMODEL, ln1b + l * DMODEL, h);

        gemm_tf32_kernel<1><<<dim3(DFF / 128, MROWS / 128), 256>>>(
            h, W1 + (size_t)l * DMODEL * DFF, ff,
            MROWS, DFF, DMODEL, b1 + l * DFF, nullptr);

        gemm_tf32_kernel<3><<<dim3(DMODEL / 128, MROWS / 128), 256>>>(
            ff, W2 + (size_t)l * DFF * DMODEL, tmp,
            MROWS, DMODEL, DFF, b2 + l * DMODEL, h);

        ln_kernel<<<MROWS, 128>>>(tmp, ln2g + l * DMODEL, ln2b + l * DMODEL,
                                  (l == NLAYER - 1) ? out : h);
    }
}

// round 5
// speedup vs baseline: 3.1155x; 3.1155x over previous
#include <cuda_runtime.h>
#include <math.h>
#include <stdint.h>

#define QLEN 1024
#define MLEN 1024
#define BSZ 4
#define DMODEL 512
#define NH 8
#define DHEAD 64
#define DFF 2048
#define NLAYER 3
#define KLEN (QLEN + MLEN)
#define MROWS (QLEN * BSZ)   /* 4096 */
#define CROWS (KLEN * BSZ)   /* 8192 */

// ---------------- scratch (device globals; no allocation allowed) -------------
static __device__ float g_h[MROWS * DMODEL];
static __device__ float g_c[CROWS * DMODEL];
static __device__ float g_q[MROWS * DMODEL];
static __device__ float g_kv[CROWS * 2 * DMODEL];
static __device__ float g_vec[MROWS * DMODEL];
static __device__ float g_ff[MROWS * DFF];
static __device__ float g_tmp[MROWS * DMODEL];

// ---------------- helpers ------------------------------------------------------
__device__ __forceinline__ uint32_t f2tf(float x) {
    uint32_t r;
    asm("cvt.rna.tf32.f32 %0, %1;" : "=r"(r) : "f"(x));
    return r;
}

__device__ __forceinline__ void mma_tf32(float* c, const uint32_t* a, const uint32_t* b) {
    asm volatile(
        "mma.sync.aligned.m16n8k8.row.col.f32.tf32.tf32.f32 "
        "{%0,%1,%2,%3}, {%4,%5,%6,%7}, {%8,%9}, {%0,%1,%2,%3};"
        : "+f"(c[0]), "+f"(c[1]), "+f"(c[2]), "+f"(c[3])
        : "r"(a[0]), "r"(a[1]), "r"(a[2]), "r"(a[3]), "r"(b[0]), "r"(b[1]));
}

__device__ __forceinline__ void cp16(void* smem, const void* gmem) {
    uint32_t s = (uint32_t)__cvta_generic_to_shared(smem);
    asm volatile("cp.async.ca.shared.global [%0], [%1], 16;\n" :: "r"(s), "l"(gmem));
}
#define CP_COMMIT() asm volatile("cp.async.commit_group;\n" ::: "memory")
#define CP_WAIT1()  asm volatile("cp.async.wait_group 1;\n" ::: "memory")
#define CP_WAIT0()  asm volatile("cp.async.wait_group 0;\n" ::: "memory")

// ---------------- embedding + sinusoidal position -----------------------------
__global__ void embed_kernel(const int* __restrict__ inp,
                             const float* __restrict__ emb,
                             float* __restrict__ h) {
    int idx = blockIdx.x * blockDim.x + threadIdx.x;
    if (idx >= MROWS * DMODEL) return;
    int d   = idx & (DMODEL - 1);
    int row = idx >> 9;
    int i   = row >> 2;
    int tok = inp[row];
    float val = emb[(size_t)tok * DMODEL + d] * 22.62741699796952f;
    float pos = (float)(QLEN - 1 - i);
    int j = (d < DMODEL / 2) ? d : d - DMODEL / 2;
    float f = powf(10000.0f, -(float)j * (1.0f / 256.0f));
    float ang = pos * f;
    val += (d < DMODEL / 2) ? sinf(ang) : cosf(ang);
    h[idx] = val;
}

// ---------------- concat ------------------------------------------------------
__global__ void concat_kernel(const float* __restrict__ mems_l,
                              const float* __restrict__ h,
                              float* __restrict__ c) {
    const int nhalf = MROWS * DMODEL / 4;
    int idx = blockIdx.x * blockDim.x + threadIdx.x;
    if (idx >= 2 * nhalf) return;
    float4 v = (idx < nhalf) ? ((const float4*)mems_l)[idx]
                             : ((const float4*)h)[idx - nhalf];
    ((float4*)c)[idx] = v;
}

// ---------------- TF32 GEMM, cp.async pipeline: 128x128x16 --------------------
// EPI: 0 = none, 1 = relu(x + bias), 2 = x + res, 3 = x + bias + res
template <int EPI>
__global__ __launch_bounds__(256, 2)
void gemm_tf32_kernel(const float* __restrict__ A, const float* __restrict__ B,
                      float* __restrict__ C, int M, int N, int K,
                      const float* __restrict__ bias, const float* __restrict__ res) {
    __shared__ __align__(16) float As[2][128][20];   // [m][k] stride 20
    __shared__ __align__(16) float Bs[2][16][136];   // [k][n] stride 136

    const int t    = threadIdx.x;
    const int lane = t & 31;
    const int warp = t >> 5;
    const int wm   = warp & 3;
    const int wn   = warp >> 2;
    const int lr   = lane >> 2;
    const int lc   = lane & 3;
    const int bm   = blockIdx.y * 128, bn = blockIdx.x * 128;
    const int m0   = wm * 32, n0 = wn * 64;

    const int amA = t >> 2;             // 0..63 (A row), +64 second
    const int akA = (t & 3) * 4;        // 0,4,8,12
    const int bkB = t >> 5;             // 0..7, +8 second
    const int bnB = (t & 31) * 4;       // 0..124

    const float* Aptr = A + (size_t)(bm + amA) * K + akA;
    const float* Bptr = B + (size_t)bkB * N + bn + bnB;
    const size_t Astep64 = (size_t)64 * K;
    const size_t Bstep8  = (size_t)8 * N;

    float acc[2][8][4];
#pragma unroll
    for (int i = 0; i < 2; i++)
#pragma unroll
        for (int j = 0; j < 8; j++)
#pragma unroll
            for (int r = 0; r < 4; r++) acc[i][j][r] = 0.0f;

    const int KB = K >> 4;

    // prologue: issue buffers 0 and 1
    cp16(&As[0][amA][akA], Aptr);
    cp16(&As[0][amA + 64][akA], Aptr + Astep64);
    cp16(&Bs[0][bkB][bnB], Bptr);
    cp16(&Bs[0][bkB + 8][bnB], Bptr + Bstep8);
    CP_COMMIT();
    if (KB > 1) {
        cp16(&As[1][amA][akA], Aptr + 16);
        cp16(&As[1][amA + 64][akA], Aptr + Astep64 + 16);
        cp16(&Bs[1][bkB][bnB], Bptr + Bstep8 * 2);
        cp16(&Bs[1][bkB + 8][bnB], Bptr + Bstep8 * 3);
        CP_COMMIT();
    }

    for (int kb = 0; kb < KB; kb++) {
        const int buf = kb & 1;
        if (kb + 1 < KB) CP_WAIT1(); else CP_WAIT0();
        __syncthreads();
#pragma unroll
        for (int ks = 0; ks < 2; ks++) {
            const int k0 = ks * 8;
            uint32_t af[2][4];
#pragma unroll
            for (int mt = 0; mt < 2; mt++) {
                int mr = m0 + mt * 16 + lr;
                af[mt][0] = __float_as_uint(As[buf][mr][k0 + lc]);
                af[mt][1] = __float_as_uint(As[buf][mr + 8][k0 + lc]);
                af[mt][2] = __float_as_uint(As[buf][mr][k0 + lc + 4]);
                af[mt][3] = __float_as_uint(As[buf][mr + 8][k0 + lc + 4]);
            }
#pragma unroll
            for (int nt = 0; nt < 8; nt++) {
                uint32_t bf[2];
                int nc = n0 + nt * 8 + lr;
                bf[0] = __float_as_uint(Bs[buf][k0 + lc][nc]);
                bf[1] = __float_as_uint(Bs[buf][k0 + lc + 4][nc]);
                mma_tf32(acc[0][nt], af[0], bf);
                mma_tf32(acc[1][nt], af[1], bf);
            }
        }
        __syncthreads();
        if (kb + 2 < KB) {
            const float* Ap = Aptr + (kb + 2) * 16;
            const float* Bp = Bptr + (size_t)(kb + 2) * 16 * N;
            cp16(&As[buf][amA][akA], Ap);
            cp16(&As[buf][amA + 64][akA], Ap + Astep64);
            cp16(&Bs[buf][bkB][bnB], Bp);
            cp16(&Bs[buf][bkB + 8][bnB], Bp + Bstep8);
            CP_COMMIT();
        }
    }

#pragma unroll
    for (int mt = 0; mt < 2; mt++) {
#pragma unroll
        for (int half = 0; half < 2; half++) {
            int row = bm + m0 + mt * 16 + lr + half * 8;
            float* Crow = C + (size_t)row * N + bn;
            const float* Rrow = (EPI >= 2) ? (res + (size_t)row * N + bn) : nullptr;
#pragma unroll
            for (int nt = 0; nt < 8; nt++) {
                int col = n0 + nt * 8 + lc * 2;
                float2 v = make_float2(acc[mt][nt][half * 2], acc[mt][nt][half * 2 + 1]);
                if (EPI == 1 || EPI == 3) {
                    float2 bb = *(const float2*)(bias + bn + col);
                    v.x += bb.x; v.y += bb.y;
                }
                if (EPI == 1) { v.x = fmaxf(v.x, 0.f); v.y = fmaxf(v.y, 0.f); }
                if (EPI >= 2) {
                    float2 rr = *(const float2*)(Rrow + col);
                    v.x += rr.x; v.y += rr.y;
                }
                *(float2*)&Crow[col] = v;
            }
        }
    }
}

// ---------------- tensor-core flash attention ---------------------------------
// grid: (QLEN/64, BSZ, NH), 256 threads (8 warps). Tiles: 64 q x 32 k.
// S^T = K @ Q^T via mma (K natural layout); softmax in fp32; O += P @ V via mma.
__global__ __launch_bounds__(256)
void attn_tc_kernel(const float* __restrict__ Q, const float* __restrict__ KV,
                    float* __restrict__ Vout) {
    __shared__ float Qs[64][65];     // init only (tf32 bits)
    __shared__ float Ks[32][68];     // tf32 bits, conflict-free A-frag (stride 68)
    __shared__ float Vs[32][72];     // tf32 bits, conflict-free B-frag (stride 72)
    __shared__ float Ss[64][36];     // scores/probs (stride 36)
    __shared__ float m_s[64], l_s[64], al_s[64];

    const int qb = blockIdx.x, b = blockIdx.y, hh = blockIdx.z;
    const int t = threadIdx.x, lane = t & 31, warp = t >> 5;
    const int lr = lane >> 2, lc = lane & 3;

    // QK phase mapping: S^T is [32 kj][64 q]
    const int mt_k = warp & 1;           // kj tile base mt_k*16
    const int nq0  = (warp >> 1) * 16;   // q columns (two n-tiles of 8)
    // PV phase mapping: O is [64 q][64 d]
    const int mq0 = (warp & 3) * 16;     // q rows
    const int nd0 = (warp >> 2) * 32;    // d cols (four n-tiles of 8)

    // load Q tile as tf32 bits
    for (int idx = t; idx < 64 * 16; idx += 256) {
        int qi = idx >> 4, d4 = (idx & 15) * 4;
        float4 v = *(const float4*)&Q[((size_t)((qb * 64 + qi) * BSZ + b)) * DMODEL
                                      + hh * DHEAD + d4];
        Qs[qi][d4 + 0] = __uint_as_float(f2tf(v.x));
        Qs[qi][d4 + 1] = __uint_as_float(f2tf(v.y));
        Qs[qi][d4 + 2] = __uint_as_float(f2tf(v.z));
        Qs[qi][d4 + 3] = __uint_as_float(f2tf(v.w));
    }
    if (t < 64) { m_s[t] = -INFINITY; l_s[t] = 0.0f; }
    __syncthreads();

    // preload Q B-fragments (B[k=d][n=q] -> Qs[q][d]); persist across all tiles
    uint32_t qf[2][8][2];
#pragma unroll
    for (int nt = 0; nt < 2; nt++)
#pragma unroll
        for (int c = 0; c < 8; c++) {
            int qcol = nq0 + nt * 8 + lr;
            qf[nt][c][0] = __float_as_uint(Qs[qcol][c * 8 + lc]);
            qf[nt][c][1] = __float_as_uint(Qs[qcol][c * 8 + lc + 4]);
        }

    float oacc[4][4];
#pragma unroll
    for (int i = 0; i < 4; i++)
#pragma unroll
        for (int j = 0; j < 4; j++) oacc[i][j] = 0.0f;

    const int nTiles    = 34 + 2 * qb;
    const int firstMask = 32 + 2 * qb;

    for (int tile = 0; tile < nTiles; tile++) {
        const int j0 = tile * 32;
        __syncthreads();   // protect Ks/Vs/Ss from previous iteration readers
        for (int idx = t; idx < 32 * 16; idx += 256) {
            int kj = idx >> 4, d4 = (idx & 15) * 4;
            size_t base = ((size_t)(j0 + kj) * BSZ + b) * (2 * DMODEL) + hh * DHEAD + d4;
            float4 kk = *(const float4*)&KV[base];
            float4 vv = *(const float4*)&KV[base + DMODEL];
            Ks[kj][d4 + 0] = __uint_as_float(f2tf(kk.x));
            Ks[kj][d4 + 1] = __uint_as_float(f2tf(kk.y));
            Ks[kj][d4 + 2] = __uint_as_float(f2tf(kk.z));
            Ks[kj][d4 + 3] = __uint_as_float(f2tf(kk.w));
            Vs[kj][d4 + 0] = __uint_as_float(f2tf(vv.x));
            Vs[kj][d4 + 1] = __uint_as_float(f2tf(vv.y));
            Vs[kj][d4 + 2] = __uint_as_float(f2tf(vv.z));
            Vs[kj][d4 + 3] = __uint_as_float(f2tf(vv.w));
        }
        __syncthreads();

        // S^T = K @ Q^T : per warp 2 n-tiles x 8 d-chunks
        float sacc[2][4] = {{0, 0, 0, 0}, {0, 0, 0, 0}};
#pragma unroll
        for (int c = 0; c < 8; c++) {
            uint32_t af[4];
            af[0] = __float_as_uint(Ks[mt_k * 16 + lr][c * 8 + lc]);
            af[1] = __float_as_uint(Ks[mt_k * 16 + 8 + lr][c * 8 + lc]);
            af[2] = __float_as_uint(Ks[mt_k * 16 + lr][c * 8 + lc + 4]);
            af[3] = __float_as_uint(Ks[mt_k * 16 + 8 + lr][c * 8 + lc + 4]);
            mma_tf32(sacc[0], af, qf[0][c]);
            mma_tf32(sacc[1], af, qf[1][c]);
        }
        // scatter S^T -> Ss[q][kj] with scale + mask
        const bool maskTile = (tile >= firstMask);
#pragma unroll
        for (int nt = 0; nt < 2; nt++)
#pragma unroll
            for (int i = 0; i < 4; i++) {
                int kjl = mt_k * 16 + lr + ((i >> 1) ? 8 : 0);
                int ql  = nq0 + nt * 8 + 2 * lc + (i & 1);
                float v = sacc[nt][i] * 0.125f;
                if (maskTile && (j0 + kjl > MLEN + qb * 64 + ql)) v = -INFINITY;
                Ss[ql][kjl] = v;
            }
        __syncthreads();

        // online softmax; lane (srow, sq) handles columns {4j + sq}
        {
            int srow = t >> 2, sq = t & 3;
            float sv[8];
            float mx = -INFINITY;
#pragma unroll
            for (int j = 0; j < 8; j++) { sv[j] = Ss[srow][4 * j + sq]; mx = fmaxf(mx, sv[j]); }
            mx = fmaxf(mx, __shfl_xor_sync(0xffffffffu, mx, 1));
            mx = fmaxf(mx, __shfl_xor_sync(0xffffffffu, mx, 2));
            float mOld = m_s[srow];
            float mNew = fmaxf(mOld, mx);
            float al   = expf(mOld - mNew);
            float sum = 0.0f;
#pragma unroll
            for (int j = 0; j < 8; j++) {
                float p = expf(sv[j] - mNew);
                Ss[srow][4 * j + sq] = __uint_as_float(f2tf(p));
                sum += p;
            }
            sum += __shfl_xor_sync(0xffffffffu, sum, 1);
            sum += __shfl_xor_sync(0xffffffffu, sum, 2);
            if (sq == 0) { m_s[srow] = mNew; l_s[srow] = l_s[srow] * al + sum; al_s[srow] = al; }
        }
        __syncthreads();

        // O += P @ V : per warp 4 n-tiles (d) x 4 kj-chunks
        float a0 = al_s[mq0 + lr], a1 = al_s[mq0 + 8 + lr];
#pragma unroll
        for (int nt = 0; nt < 4; nt++) {
            oacc[nt][0] *= a0; oacc[nt][1] *= a0;
            oacc[nt][2] *= a1; oacc[nt][3] *= a1;
        }
#pragma unroll
        for (int c = 0; c < 4; c++) {
            uint32_t af[4];
            af[0] = __float_as_uint(Ss[mq0 + lr][c * 8 + lc]);
            af[1] = __float_as_uint(Ss[mq0 + 8 + lr][c * 8 + lc]);
            af[2] = __float_as_uint(Ss[mq0 + lr][c * 8 + lc + 4]);
            af[3] = __float_as_uint(Ss[mq0 + 8 + lr][c * 8 + lc + 4]);
#pragma unroll
            for (int nt = 0; nt < 4; nt++) {
                uint32_t bf[2];
                bf[0] = __float_as_uint(Vs[c * 8 + lc][nd0 + nt * 8 + lr]);
                bf[1] = __float_as_uint(Vs[c * 8 + lc + 4][nd0 + nt * 8 + lr]);
                mma_tf32(oacc[nt], af, bf);
            }
        }
    }

    // final normalize + store
#pragma unroll
    for (int half = 0; half < 2; half++) {
        int q = mq0 + lr + half * 8;
        float invl = 1.0f / l_s[q];
        float* orow = &Vout[((size_t)((qb * 64 + q) * BSZ + b)) * DMODEL + hh * DHEAD];
#pragma unroll
        for (int nt = 0; nt < 4; nt++) {
            float2 v = make_float2(oacc[nt][half * 2] * invl, oacc[nt][half * 2 + 1] * invl);
            *(float2*)&orow[nd0 + nt * 8 + 2 * lc] = v;
        }
    }
}

// ---------------- layernorm ---------------------------------------------------
__global__ __launch_bounds__(128)
void ln_kernel(const float* __restrict__ x, const float* __restrict__ g,
               const float* __restrict__ bparm, float* __restrict__ out) {
    const int row = blockIdx.x;
    const int t = threadIdx.x;
    float4 v = ((const float4*)(x + (size_t)row * DMODEL))[t];
    float s  = v.x + v.y + v.z + v.w;
    float s2 = fmaf(v.x, v.x, fmaf(v.y, v.y, fmaf(v.z, v.z, v.w * v.w)));
#pragma unroll
    for (int o = 16; o > 0; o >>= 1) {
        s  += __shfl_down_sync(0xffffffffu, s, o);
        s2 += __shfl_down_sync(0xffffffffu, s2, o);
    }
    __shared__ float ss[4], ss2[4];
    int w = t >> 5;
    if ((t & 31) == 0) { ss[w] = s; ss2[w] = s2; }
    __syncthreads();
    float tot  = ss[0] + ss[1] + ss[2] + ss[3];
    float tot2 = ss2[0] + ss2[1] + ss2[2] + ss2[3];
    float mu  = tot * (1.0f / DMODEL);
    float var = tot2 * (1.0f / DMODEL) - mu * mu;
    float rs  = rsqrtf(var + 1e-5f);
    float4 gg = ((const float4*)g)[t];
    float4 bb = ((const float4*)bparm)[t];
    float4 o;
    o.x = (v.x - mu) * rs * gg.x + bb.x;
    o.y = (v.y - mu) * rs * gg.y + bb.y;
    o.z = (v.z - mu) * rs * gg.z + bb.z;
    o.w = (v.w - mu) * rs * gg.w + bb.w;
    ((float4*)(out + (size_t)row * DMODEL))[t] = o;
}

// ---------------- launch ------------------------------------------------------
extern "C" void kernel_launch(void* const* d_in, const int* in_sizes, int n_in,
                              void* d_out, int out_size) {
    const int*   inp  = (const int*)d_in[0];
    const float* emb  = (const float*)d_in[1];
    const float* mems = (const float*)d_in[2];
    const float* Wq   = (const float*)d_in[3];
    const float* Wkv  = (const float*)d_in[4];
    const float* Wo   = (const float*)d_in[5];
    const float* ln1g = (const float*)d_in[6];
    const float* ln1b = (const float*)d_in[7];
    const float* W1   = (const float*)d_in[8];
    const float* b1   = (const float*)d_in[9];
    const float* W2   = (const float*)d_in[10];
    const float* b2   = (const float*)d_in[11];
    const float* ln2g = (const float*)d_in[12];
    const float* ln2b = (const float*)d_in[13];
    float* out = (float*)d_out;

    float *h, *c, *q, *kv, *vec, *ff, *tmp;
    cudaGetSymbolAddress((void**)&h,   g_h);
    cudaGetSymbolAddress((void**)&c,   g_c);
    cudaGetSymbolAddress((void**)&q,   g_q);
    cudaGetSymbolAddress((void**)&kv,  g_kv);
    cudaGetSymbolAddress((void**)&vec, g_vec);
    cudaGetSymbolAddress((void**)&ff,  g_ff);
    cudaGetSymbolAddress((void**)&tmp, g_tmp);

    embed_kernel<<<(MROWS * DMODEL + 255) / 256, 256>>>(inp, emb, h);

    for (int l = 0; l < NLAYER; l++) {
        concat_kernel<<<(CROWS * DMODEL / 4 + 255) / 256, 256>>>(
            mems + (size_t)l * MLEN * BSZ * DMODEL, h, c);

        gemm_tf32_kernel<0><<<dim3(DMODEL / 128, MROWS / 128), 256>>>(
            h, Wq + (size_t)l * DMODEL * DMODEL, q,
            MROWS, DMODEL, DMODEL, nullptr, nullptr);

        gemm_tf32_kernel<0><<<dim3(2 * DMODEL / 128, CROWS / 128), 256>>>(
            c, Wkv + (size_t)l * DMODEL * 2 * DMODEL, kv,
            CROWS, 2 * DMODEL, DMODEL, nullptr, nullptr);

        attn_tc_kernel<<<dim3(QLEN / 64, BSZ, NH), 256>>>(q, kv, vec);

        gemm_tf32_kernel<2><<<dim3(DMODEL / 128, MROWS / 128), 256>>>(
            vec, Wo + (size_t)l * DMODEL * DMODEL, tmp,
            MROWS, DMODEL, DMODEL, nullptr, h);

        ln_kernel<<<MROWS, 128>>>(tmp, ln1g + l * DMODEL, ln1b + l * DMODEL, h);

        gemm_tf32_kernel<1><<<dim3(DFF / 128, MROWS / 128), 256>>>(
            h, W1 + (size_t)l * DMODEL * DFF, ff,
            MROWS, DFF, DMODEL, b1 + l * DFF, nullptr);

        gemm_tf32_kernel<3><<<dim3(DMODEL / 128, MROWS / 128), 256>>>(
            ff, W2 + (size_t)l * DFF * DMODEL, tmp,
            MROWS, DMODEL, DFF, b2 + l * DMODEL, h);

        ln_kernel<<<MROWS, 128>>>(tmp, ln2g + l * DMODEL, ln2b + l * DMODEL,
                                  (l == NLAYER - 1) ? out : h);
    }
}

// round 6
// speedup vs baseline: 3.2577x; 1.0457x over previous
#include <cuda_runtime.h>
#include <math.h>
#include <stdint.h>

#define QLEN 1024
#define MLEN 1024
#define BSZ 4
#define DMODEL 512
#define NH 8
#define DHEAD 64
#define DFF 2048
#define NLAYER 3
#define KLEN (QLEN + MLEN)
#define MROWS (QLEN * BSZ)   /* 4096 */
#define CROWS (KLEN * BSZ)   /* 8192 */

// ---------------- scratch (device globals; no allocation allowed) -------------
static __device__ float g_h[MROWS * DMODEL];
static __device__ float g_c[CROWS * DMODEL];
static __device__ float g_q[MROWS * DMODEL];
static __device__ float g_kv[CROWS * 2 * DMODEL];
static __device__ float g_vec[MROWS * DMODEL];
static __device__ float g_ff[MROWS * DFF];
static __device__ float g_tmp[MROWS * DMODEL];

// ---------------- helpers ------------------------------------------------------
__device__ __forceinline__ uint32_t f2tf(float x) {
    uint32_t r;
    asm("cvt.rna.tf32.f32 %0, %1;" : "=r"(r) : "f"(x));
    return r;
}

__device__ __forceinline__ void mma_tf32(float* c, const uint32_t* a, const uint32_t* b) {
    asm volatile(
        "mma.sync.aligned.m16n8k8.row.col.f32.tf32.tf32.f32 "
        "{%0,%1,%2,%3}, {%4,%5,%6,%7}, {%8,%9}, {%0,%1,%2,%3};"
        : "+f"(c[0]), "+f"(c[1]), "+f"(c[2]), "+f"(c[3])
        : "r"(a[0]), "r"(a[1]), "r"(a[2]), "r"(a[3]), "r"(b[0]), "r"(b[1]));
}

__device__ __forceinline__ void cp16(void* smem, const void* gmem) {
    uint32_t s = (uint32_t)__cvta_generic_to_shared(smem);
    asm volatile("cp.async.ca.shared.global [%0], [%1], 16;\n" :: "r"(s), "l"(gmem));
}
#define CP_COMMIT() asm volatile("cp.async.commit_group;\n" ::: "memory")
#define CP_WAIT1()  asm volatile("cp.async.wait_group 1;\n" ::: "memory")
#define CP_WAIT0()  asm volatile("cp.async.wait_group 0;\n" ::: "memory")

// ---------------- embedding + sinusoidal position -----------------------------
__global__ void embed_kernel(const int* __restrict__ inp,
                             const float* __restrict__ emb,
                             float* __restrict__ h) {
    int idx = blockIdx.x * blockDim.x + threadIdx.x;
    if (idx >= MROWS * DMODEL) return;
    int d   = idx & (DMODEL - 1);
    int row = idx >> 9;
    int i   = row >> 2;
    int tok = inp[row];
    float val = emb[(size_t)tok * DMODEL + d] * 22.62741699796952f;
    float pos = (float)(QLEN - 1 - i);
    int j = (d < DMODEL / 2) ? d : d - DMODEL / 2;
    float f = powf(10000.0f, -(float)j * (1.0f / 256.0f));
    float ang = pos * f;
    val += (d < DMODEL / 2) ? sinf(ang) : cosf(ang);
    h[idx] = val;
}

// ---------------- concat ------------------------------------------------------
__global__ void concat_kernel(const float* __restrict__ mems_l,
                              const float* __restrict__ h,
                              float* __restrict__ c) {
    const int nhalf = MROWS * DMODEL / 4;
    int idx = blockIdx.x * blockDim.x + threadIdx.x;
    if (idx >= 2 * nhalf) return;
    float4 v = (idx < nhalf) ? ((const float4*)mems_l)[idx]
                             : ((const float4*)h)[idx - nhalf];
    ((float4*)c)[idx] = v;
}

// ---------------- TF32 GEMM, 3-stage cp.async ring: 128x128x16 ----------------
// EPI: 0 = none, 1 = relu(x + bias), 2 = x + res, 3 = x + bias + res
// Per stage: A tile 128x20 floats (stride-20, conflict-free), B tile 16x136.
#define G_ASZ  (128 * 20)          /* 2560 floats */
#define G_BSZ  (16 * 136)          /* 2176 floats */
#define G_STG  (G_ASZ + G_BSZ)     /* 4736 floats per stage */
#define G_SMEM (3 * G_STG * 4)     /* 56832 bytes */

template <int EPI>
__global__ __launch_bounds__(256, 2)
void gemm_tf32_kernel(const float* __restrict__ A, const float* __restrict__ B,
                      float* __restrict__ C, int M, int N, int K,
                      const float* __restrict__ bias, const float* __restrict__ res) {
    extern __shared__ __align__(16) float sm[];

    const int t    = threadIdx.x;
    const int lane = t & 31;
    const int warp = t >> 5;
    const int wm   = warp & 3;
    const int wn   = warp >> 2;
    const int lr   = lane >> 2;
    const int lc   = lane & 3;
    const int bm   = blockIdx.y * 128, bn = blockIdx.x * 128;
    const int m0   = wm * 32, n0 = wn * 64;

    const int amA = t >> 2;             // 0..63 (A row), +64 second
    const int akA = (t & 3) * 4;        // 0,4,8,12
    const int bkB = t >> 5;             // 0..7, +8 second
    const int bnB = (t & 31) * 4;       // 0..124

    const float* Aptr = A + (size_t)(bm + amA) * K + akA;
    const float* Bptr = B + (size_t)bkB * N + bn + bnB;
    const size_t Astep64 = (size_t)64 * K;
    const size_t Bstep8  = (size_t)8 * N;

    // per-thread smem write offsets within a stage
    const int aOff0 = amA * 20 + akA;
    const int aOff1 = (amA + 64) * 20 + akA;
    const int bOff0 = G_ASZ + bkB * 136 + bnB;
    const int bOff1 = G_ASZ + (bkB + 8) * 136 + bnB;

    float acc[2][8][4];
#pragma unroll
    for (int i = 0; i < 2; i++)
#pragma unroll
        for (int j = 0; j < 8; j++)
#pragma unroll
            for (int r = 0; r < 4; r++) acc[i][j][r] = 0.0f;

    const int KB = K >> 4;

    // prologue: stages 0 and 1
#pragma unroll
    for (int s = 0; s < 2; s++) {
        float* st = sm + s * G_STG;
        const float* Ap = Aptr + s * 16;
        const float* Bp = Bptr + (size_t)s * 16 * N;
        cp16(st + aOff0, Ap);
        cp16(st + aOff1, Ap + Astep64);
        cp16(st + bOff0, Bp);
        cp16(st + bOff1, Bp + Bstep8);
        CP_COMMIT();
    }

    int rbuf = 0, wbuf = 2;
    for (int kb = 0; kb < KB; kb++) {
        if (kb + 1 < KB) CP_WAIT1(); else CP_WAIT0();
        __syncthreads();

        // issue next stage before compute (write target != read, != in-flight)
        if (kb + 2 < KB) {
            float* st = sm + wbuf * G_STG;
            const float* Ap = Aptr + (kb + 2) * 16;
            const float* Bp = Bptr + (size_t)(kb + 2) * 16 * N;
            cp16(st + aOff0, Ap);
            cp16(st + aOff1, Ap + Astep64);
            cp16(st + bOff0, Bp);
            cp16(st + bOff1, Bp + Bstep8);
            CP_COMMIT();
        }

        const float* As_ = sm + rbuf * G_STG;
        const float* Bs_ = As_ + G_ASZ;
#pragma unroll
        for (int ks = 0; ks < 2; ks++) {
            const int k0 = ks * 8;
            uint32_t af[2][4];
#pragma unroll
            for (int mt = 0; mt < 2; mt++) {
                int mr = m0 + mt * 16 + lr;
                af[mt][0] = __float_as_uint(As_[mr * 20 + k0 + lc]);
                af[mt][1] = __float_as_uint(As_[(mr + 8) * 20 + k0 + lc]);
                af[mt][2] = __float_as_uint(As_[mr * 20 + k0 + lc + 4]);
                af[mt][3] = __float_as_uint(As_[(mr + 8) * 20 + k0 + lc + 4]);
            }
#pragma unroll
            for (int nt = 0; nt < 8; nt++) {
                uint32_t bf[2];
                int nc = n0 + nt * 8 + lr;
                bf[0] = __float_as_uint(Bs_[(k0 + lc) * 136 + nc]);
                bf[1] = __float_as_uint(Bs_[(k0 + lc + 4) * 136 + nc]);
                mma_tf32(acc[0][nt], af[0], bf);
                mma_tf32(acc[1][nt], af[1], bf);
            }
        }
        rbuf = (rbuf + 1) % 3;
        wbuf = (wbuf + 1) % 3;
    }

#pragma unroll
    for (int mt = 0; mt < 2; mt++) {
#pragma unroll
        for (int half = 0; half < 2; half++) {
            int row = bm + m0 + mt * 16 + lr + half * 8;
            float* Crow = C + (size_t)row * N + bn;
            const float* Rrow = (EPI >= 2) ? (res + (size_t)row * N + bn) : nullptr;
#pragma unroll
            for (int nt = 0; nt < 8; nt++) {
                int col = n0 + nt * 8 + lc * 2;
                float2 v = make_float2(acc[mt][nt][half * 2], acc[mt][nt][half * 2 + 1]);
                if (EPI == 1 || EPI == 3) {
                    float2 bb = *(const float2*)(bias + bn + col);
                    v.x += bb.x; v.y += bb.y;
                }
                if (EPI == 1) { v.x = fmaxf(v.x, 0.f); v.y = fmaxf(v.y, 0.f); }
                if (EPI >= 2) {
                    float2 rr = *(const float2*)(Rrow + col);
                    v.x += rr.x; v.y += rr.y;
                }
                *(float2*)&Crow[col] = v;
            }
        }
    }
}

// ---------------- tensor-core flash attention ---------------------------------
// grid: (QLEN/64, BSZ, NH), 256 threads (8 warps). Tiles: 64 q x 32 k.
// KV gmem loads software-pipelined one tile ahead in registers.
__global__ __launch_bounds__(256)
void attn_tc_kernel(const float* __restrict__ Q, const float* __restrict__ KV,
                    float* __restrict__ Vout) {
    __shared__ float Qs[64][65];     // init only (tf32 bits)
    __shared__ float Ks[32][68];     // tf32 bits, conflict-free A-frag
    __shared__ float Vs[32][72];     // tf32 bits, conflict-free B-frag
    __shared__ float Ss[64][36];     // scores/probs
    __shared__ float m_s[64], l_s[64], al_s[64];

    const int qb = blockIdx.x, b = blockIdx.y, hh = blockIdx.z;
    const int t = threadIdx.x, lane = t & 31, warp = t >> 5;
    const int lr = lane >> 2, lc = lane & 3;

    const int mt_k = warp & 1;           // QK: kj tile base mt_k*16
    const int nq0  = (warp >> 1) * 16;   // QK: q columns
    const int mq0 = (warp & 3) * 16;     // PV: q rows
    const int nd0 = (warp >> 2) * 32;    // PV: d cols

    // KV pipeline mapping: thread t handles rows kjA and kjA+16, cols d4A..d4A+3
    const int kjA = t >> 4;              // 0..15
    const int d4A = (t & 15) * 4;

    // load Q tile as tf32 bits
    for (int idx = t; idx < 64 * 16; idx += 256) {
        int qi = idx >> 4, d4 = (idx & 15) * 4;
        float4 v = *(const float4*)&Q[((size_t)((qb * 64 + qi) * BSZ + b)) * DMODEL
                                      + hh * DHEAD + d4];
        Qs[qi][d4 + 0] = __uint_as_float(f2tf(v.x));
        Qs[qi][d4 + 1] = __uint_as_float(f2tf(v.y));
        Qs[qi][d4 + 2] = __uint_as_float(f2tf(v.z));
        Qs[qi][d4 + 3] = __uint_as_float(f2tf(v.w));
    }
    if (t < 64) { m_s[t] = -INFINITY; l_s[t] = 0.0f; }
    __syncthreads();

    // preload Q B-fragments; persist across all tiles
    uint32_t qf[2][8][2];
#pragma unroll
    for (int nt = 0; nt < 2; nt++)
#pragma unroll
        for (int c = 0; c < 8; c++) {
            int qcol = nq0 + nt * 8 + lr;
            qf[nt][c][0] = __float_as_uint(Qs[qcol][c * 8 + lc]);
            qf[nt][c][1] = __float_as_uint(Qs[qcol][c * 8 + lc + 4]);
        }

    float oacc[4][4];
#pragma unroll
    for (int i = 0; i < 4; i++)
#pragma unroll
        for (int j = 0; j < 4; j++) oacc[i][j] = 0.0f;

    const int nTiles    = 34 + 2 * qb;
    const int firstMask = 32 + 2 * qb;

    // prologue: KV tile 0 into registers
    float4 kr0, kr1, vr0, vr1;
    {
        size_t b0 = ((size_t)kjA * BSZ + b) * (2 * DMODEL) + hh * DHEAD + d4A;
        size_t b1 = ((size_t)(kjA + 16) * BSZ + b) * (2 * DMODEL) + hh * DHEAD + d4A;
        kr0 = *(const float4*)&KV[b0];          vr0 = *(const float4*)&KV[b0 + DMODEL];
        kr1 = *(const float4*)&KV[b1];          vr1 = *(const float4*)&KV[b1 + DMODEL];
    }

    for (int tile = 0; tile < nTiles; tile++) {
        const int j0 = tile * 32;
        __syncthreads();   // previous tile's readers of Ks/Vs/Ss are done

        // stage registers -> smem (tf32)
        Ks[kjA][d4A + 0] = __uint_as_float(f2tf(kr0.x));
        Ks[kjA][d4A + 1] = __uint_as_float(f2tf(kr0.y));
        Ks[kjA][d4A + 2] = __uint_as_float(f2tf(kr0.z));
        Ks[kjA][d4A + 3] = __uint_as_float(f2tf(kr0.w));
        Ks[kjA + 16][d4A + 0] = __uint_as_float(f2tf(kr1.x));
        Ks[kjA + 16][d4A + 1] = __uint_as_float(f2tf(kr1.y));
        Ks[kjA + 16][d4A + 2] = __uint_as_float(f2tf(kr1.z));
        Ks[kjA + 16][d4A + 3] = __uint_as_float(f2tf(kr1.w));
        Vs[kjA][d4A + 0] = __uint_as_float(f2tf(vr0.x));
        Vs[kjA][d4A + 1] = __uint_as_float(f2tf(vr0.y));
        Vs[kjA][d4A + 2] = __uint_as_float(f2tf(vr0.z));
        Vs[kjA][d4A + 3] = __uint_as_float(f2tf(vr0.w));
        Vs[kjA + 16][d4A + 0] = __uint_as_float(f2tf(vr1.x));
        Vs[kjA + 16][d4A + 1] = __uint_as_float(f2tf(vr1.y));
        Vs[kjA + 16][d4A + 2] = __uint_as_float(f2tf(vr1.z));
        Vs[kjA + 16][d4A + 3] = __uint_as_float(f2tf(vr1.w));

        // prefetch next tile into the same registers (latency hides under compute)
        if (tile + 1 < nTiles) {
            size_t b0 = ((size_t)(j0 + 32 + kjA) * BSZ + b) * (2 * DMODEL) + hh * DHEAD + d4A;
            size_t b1 = ((size_t)(j0 + 48 + kjA) * BSZ + b) * (2 * DMODEL) + hh * DHEAD + d4A;
            kr0 = *(const float4*)&KV[b0];      vr0 = *(const float4*)&KV[b0 + DMODEL];
            kr1 = *(const float4*)&KV[b1];      vr1 = *(const float4*)&KV[b1 + DMODEL];
        }
        __syncthreads();

        // S^T = K @ Q^T
        float sacc[2][4] = {{0, 0, 0, 0}, {0, 0, 0, 0}};
#pragma unroll
        for (int c = 0; c < 8; c++) {
            uint32_t af[4];
            af[0] = __float_as_uint(Ks[mt_k * 16 + lr][c * 8 + lc]);
            af[1] = __float_as_uint(Ks[mt_k * 16 + 8 + lr][c * 8 + lc]);
            af[2] = __float_as_uint(Ks[mt_k * 16 + lr][c * 8 + lc + 4]);
            af[3] = __float_as_uint(Ks[mt_k * 16 + 8 + lr][c * 8 + lc + 4]);
            mma_tf32(sacc[0], af, qf[0][c]);
            mma_tf32(sacc[1], af, qf[1][c]);
        }
        const bool maskTile = (tile >= firstMask);
#pragma unroll
        for (int nt = 0; nt < 2; nt++)
#pragma unroll
            for (int i = 0; i < 4; i++) {
                int kjl = mt_k * 16 + lr + ((i >> 1) ? 8 : 0);
                int ql  = nq0 + nt * 8 + 2 * lc + (i & 1);
                float v = sacc[nt][i] * 0.125f;
                if (maskTile && (j0 + kjl > MLEN + qb * 64 + ql)) v = -INFINITY;
                Ss[ql][kjl] = v;
            }
        __syncthreads();

        // online softmax
        {
            int srow = t >> 2, sq = t & 3;
            float sv[8];
            float mx = -INFINITY;
#pragma unroll
            for (int j = 0; j < 8; j++) { sv[j] = Ss[srow][4 * j + sq]; mx = fmaxf(mx, sv[j]); }
            mx = fmaxf(mx, __shfl_xor_sync(0xffffffffu, mx, 1));
            mx = fmaxf(mx, __shfl_xor_sync(0xffffffffu, mx, 2));
            float mOld = m_s[srow];
            float mNew = fmaxf(mOld, mx);
            float al   = expf(mOld - mNew);
            float sum = 0.0f;
#pragma unroll
            for (int j = 0; j < 8; j++) {
                float p = expf(sv[j] - mNew);
                Ss[srow][4 * j + sq] = __uint_as_float(f2tf(p));
                sum += p;
            }
            sum += __shfl_xor_sync(0xffffffffu, sum, 1);
            sum += __shfl_xor_sync(0xffffffffu, sum, 2);
            if (sq == 0) { m_s[srow] = mNew; l_s[srow] = l_s[srow] * al + sum; al_s[srow] = al; }
        }
        __syncthreads();

        // O += P @ V
        float a0 = al_s[mq0 + lr], a1 = al_s[mq0 + 8 + lr];
#pragma unroll
        for (int nt = 0; nt < 4; nt++) {
            oacc[nt][0] *= a0; oacc[nt][1] *= a0;
            oacc[nt][2] *= a1; oacc[nt][3] *= a1;
        }
#pragma unroll
        for (int c = 0; c < 4; c++) {
            uint32_t af[4];
            af[0] = __float_as_uint(Ss[mq0 + lr][c * 8 + lc]);
            af[1] = __float_as_uint(Ss[mq0 + 8 + lr][c * 8 + lc]);
            af[2] = __float_as_uint(Ss[mq0 + lr][c * 8 + lc + 4]);
            af[3] = __float_as_uint(Ss[mq0 + 8 + lr][c * 8 + lc + 4]);
#pragma unroll
            for (int nt = 0; nt < 4; nt++) {
                uint32_t bf[2];
                bf[0] = __float_as_uint(Vs[c * 8 + lc][nd0 + nt * 8 + lr]);
                bf[1] = __float_as_uint(Vs[c * 8 + lc + 4][nd0 + nt * 8 + lr]);
                mma_tf32(oacc[nt], af, bf);
            }
        }
    }

    // final normalize + store
#pragma unroll
    for (int half = 0; half < 2; half++) {
        int q = mq0 + lr + half * 8;
        float invl = 1.0f / l_s[q];
        float* orow = &Vout[((size_t)((qb * 64 + q) * BSZ + b)) * DMODEL + hh * DHEAD];
#pragma unroll
        for (int nt = 0; nt < 4; nt++) {
            float2 v = make_float2(oacc[nt][half * 2] * invl, oacc[nt][half * 2 + 1] * invl);
            *(float2*)&orow[nd0 + nt * 8 + 2 * lc] = v;
        }
    }
}

// ---------------- layernorm ---------------------------------------------------
__global__ __launch_bounds__(128)
void ln_kernel(const float* __restrict__ x, const float* __restrict__ g,
               const float* __restrict__ bparm, float* __restrict__ out) {
    const int row = blockIdx.x;
    const int t = threadIdx.x;
    float4 v = ((const float4*)(x + (size_t)row * DMODEL))[t];
    float s  = v.x + v.y + v.z + v.w;
    float s2 = fmaf(v.x, v.x, fmaf(v.y, v.y, fmaf(v.z, v.z, v.w * v.w)));
#pragma unroll
    for (int o = 16; o > 0; o >>= 1) {
        s  += __shfl_down_sync(0xffffffffu, s, o);
        s2 += __shfl_down_sync(0xffffffffu, s2, o);
    }
    __shared__ float ss[4], ss2[4];
    int w = t >> 5;
    if ((t & 31) == 0) { ss[w] = s; ss2[w] = s2; }
    __syncthreads();
    float tot  = ss[0] + ss[1] + ss[2] + ss[3];
    float tot2 = ss2[0] + ss2[1] + ss2[2] + ss2[3];
    float mu  = tot * (1.0f / DMODEL);
    float var = tot2 * (1.0f / DMODEL) - mu * mu;
    float rs  = rsqrtf(var + 1e-5f);
    float4 gg = ((const float4*)g)[t];
    float4 bb = ((const float4*)bparm)[t];
    float4 o;
    o.x = (v.x - mu) * rs * gg.x + bb.x;
    o.y = (v.y - mu) * rs * gg.y + bb.y;
    o.z = (v.z - mu) * rs * gg.z + bb.z;
    o.w = (v.w - mu) * rs * gg.w + bb.w;
    ((float4*)(out + (size_t)row * DMODEL))[t] = o;
}

// ---------------- launch ------------------------------------------------------
extern "C" void kernel_launch(void* const* d_in, const int* in_sizes, int n_in,
                              void* d_out, int out_size) {
    const int*   inp  = (const int*)d_in[0];
    const float* emb  = (const float*)d_in[1];
    const float* mems = (const float*)d_in[2];
    const float* Wq   = (const float*)d_in[3];
    const float* Wkv  = (const float*)d_in[4];
    const float* Wo   = (const float*)d_in[5];
    const float* ln1g = (const float*)d_in[6];
    const float* ln1b = (const float*)d_in[7];
    const float* W1   = (const float*)d_in[8];
    const float* b1   = (const float*)d_in[9];
    const float* W2   = (const float*)d_in[10];
    const float* b2   = (const float*)d_in[11];
    const float* ln2g = (const float*)d_in[12];
    const float* ln2b = (const float*)d_in[13];
    float* out = (float*)d_out;

    float *h, *c, *q, *kv, *vec, *ff, *tmp;
    cudaGetSymbolAddress((void**)&h,   g_h);
    cudaGetSymbolAddress((void**)&c,   g_c);
    cudaGetSymbolAddress((void**)&q,   g_q);
    cudaGetSymbolAddress((void**)&kv,  g_kv);
    cudaGetSymbolAddress((void**)&vec, g_vec);
    cudaGetSymbolAddress((void**)&ff,  g_ff);
    cudaGetSymbolAddress((void**)&tmp, g_tmp);

    // dynamic smem (56.8 KB) exceeds the 48 KB default: raise the cap once per instantiation
    cudaFuncSetAttribute(gemm_tf32_kernel<0>, cudaFuncAttributeMaxDynamicSharedMemorySize, G_SMEM);
    cudaFuncSetAttribute(gemm_tf32_kernel<1>, cudaFuncAttributeMaxDynamicSharedMemorySize, G_SMEM);
    cudaFuncSetAttribute(gemm_tf32_kernel<2>, cudaFuncAttributeMaxDynamicSharedMemorySize, G_SMEM);
    cudaFuncSetAttribute(gemm_tf32_kernel<3>, cudaFuncAttributeMaxDynamicSharedMemorySize, G_SMEM);

    embed_kernel<<<(MROWS * DMODEL + 255) / 256, 256>>>(inp, emb, h);

    for (int l = 0; l < NLAYER; l++) {
        concat_kernel<<<(CROWS * DMODEL / 4 + 255) / 256, 256>>>(
            mems + (size_t)l * MLEN * BSZ * DMODEL, h, c);

        gemm_tf32_kernel<0><<<dim3(DMODEL / 128, MROWS / 128), 256, G_SMEM>>>(
            h, Wq + (size_t)l * DMODEL * DMODEL, q,
            MROWS, DMODEL, DMODEL, nullptr, nullptr);

        gemm_tf32_kernel<0><<<dim3(2 * DMODEL / 128, CROWS / 128), 256, G_SMEM>>>(
            c, Wkv + (size_t)l * DMODEL * 2 * DMODEL, kv,
            CROWS, 2 * DMODEL, DMODEL, nullptr, nullptr);

        attn_tc_kernel<<<dim3(QLEN / 64, BSZ, NH), 256>>>(q, kv, vec);

        gemm_tf32_kernel<2><<<dim3(DMODEL / 128, MROWS / 128), 256, G_SMEM>>>(
            vec, Wo + (size_t)l * DMODEL * DMODEL, tmp,
            MROWS, DMODEL, DMODEL, nullptr, h);

        ln_kernel<<<MROWS, 128>>>(tmp, ln1g + l * DMODEL, ln1b + l * DMODEL, h);

        gemm_tf32_kernel<1><<<dim3(DFF / 128, MROWS / 128), 256, G_SMEM>>>(
            h, W1 + (size_t)l * DMODEL * DFF, ff,
            MROWS, DFF, DMODEL, b1 + l * DFF, nullptr);

        gemm_tf32_kernel<3><<<dim3(DMODEL / 128, MROWS / 128), 256, G_SMEM>>>(
            ff, W2 + (size_t)l * DFF * DMODEL, tmp,
            MROWS, DMODEL, DFF, b2 + l * DMODEL, h);

        ln_kernel<<<MROWS, 128>>>(tmp, ln2g + l * DMODEL, ln2b + l * DMODEL,
                                  (l == NLAYER - 1) ? out : h);
    }
}

// round 7
// speedup vs baseline: 3.4286x; 1.0525x over previous
#include <cuda_runtime.h>
#include <math.h>
#include <stdint.h>

#define QLEN 1024
#define MLEN 1024
#define BSZ 4
#define DMODEL 512
#define NH 8
#define DHEAD 64
#define DFF 2048
#define NLAYER 3
#define KLEN (QLEN + MLEN)
#define MROWS (QLEN * BSZ)   /* 4096 */
#define CROWS (KLEN * BSZ)   /* 8192 */

// ---------------- scratch (device globals; no allocation allowed) -------------
static __device__ float g_h[MROWS * DMODEL];
static __device__ float g_c[CROWS * DMODEL];
static __device__ float g_q[MROWS * DMODEL];
static __device__ float g_kv[CROWS * 2 * DMODEL];
static __device__ float g_vec[MROWS * DMODEL];
static __device__ float g_ff[MROWS * DFF];
static __device__ float g_tmp[MROWS * DMODEL];

// ---------------- helpers ------------------------------------------------------
__device__ __forceinline__ uint32_t f2tf(float x) {
    uint32_t r;
    asm("cvt.rna.tf32.f32 %0, %1;" : "=r"(r) : "f"(x));
    return r;
}
__device__ __forceinline__ float4 tf4(float4 v) {
    return make_float4(__uint_as_float(f2tf(v.x)), __uint_as_float(f2tf(v.y)),
                       __uint_as_float(f2tf(v.z)), __uint_as_float(f2tf(v.w)));
}

__device__ __forceinline__ void mma_tf32(float* c, const uint32_t* a, const uint32_t* b) {
    asm volatile(
        "mma.sync.aligned.m16n8k8.row.col.f32.tf32.tf32.f32 "
        "{%0,%1,%2,%3}, {%4,%5,%6,%7}, {%8,%9}, {%0,%1,%2,%3};"
        : "+f"(c[0]), "+f"(c[1]), "+f"(c[2]), "+f"(c[3])
        : "r"(a[0]), "r"(a[1]), "r"(a[2]), "r"(a[3]), "r"(b[0]), "r"(b[1]));
}

__device__ __forceinline__ void cp16(void* smem, const void* gmem) {
    uint32_t s = (uint32_t)__cvta_generic_to_shared(smem);
    asm volatile("cp.async.ca.shared.global [%0], [%1], 16;\n" :: "r"(s), "l"(gmem));
}
#define CP_COMMIT() asm volatile("cp.async.commit_group;\n" ::: "memory")
#define CP_WAIT1()  asm volatile("cp.async.wait_group 1;\n" ::: "memory")
#define CP_WAIT0()  asm volatile("cp.async.wait_group 0;\n" ::: "memory")

// ---------------- embedding + sinusoidal position -----------------------------
__global__ void embed_kernel(const int* __restrict__ inp,
                             const float* __restrict__ emb,
                             float* __restrict__ h) {
    int idx = blockIdx.x * blockDim.x + threadIdx.x;
    if (idx >= MROWS * DMODEL) return;
    int d   = idx & (DMODEL - 1);
    int row = idx >> 9;
    int i   = row >> 2;
    int tok = inp[row];
    float val = emb[(size_t)tok * DMODEL + d] * 22.62741699796952f;
    float pos = (float)(QLEN - 1 - i);
    int j = (d < DMODEL / 2) ? d : d - DMODEL / 2;
    float f = powf(10000.0f, -(float)j * (1.0f / 256.0f));
    float ang = pos * f;
    val += (d < DMODEL / 2) ? sinf(ang) : cosf(ang);
    h[idx] = val;
}

// ---------------- concat ------------------------------------------------------
__global__ void concat_kernel(const float* __restrict__ mems_l,
                              const float* __restrict__ h,
                              float* __restrict__ c) {
    const int nhalf = MROWS * DMODEL / 4;
    int idx = blockIdx.x * blockDim.x + threadIdx.x;
    if (idx >= 2 * nhalf) return;
    float4 v = (idx < nhalf) ? ((const float4*)mems_l)[idx]
                             : ((const float4*)h)[idx - nhalf];
    ((float4*)c)[idx] = v;
}

// ---------------- TF32 GEMM, 3-stage cp.async ring: 128x128x16 ----------------
// EPI: 0 = none, 1 = relu(x + bias), 2 = x + res, 3 = x + bias + res
#define G_ASZ  (128 * 20)
#define G_BSZ  (16 * 136)
#define G_STG  (G_ASZ + G_BSZ)
#define G_SMEM (3 * G_STG * 4)

template <int EPI>
__global__ __launch_bounds__(256, 2)
void gemm_tf32_kernel(const float* __restrict__ A, const float* __restrict__ B,
                      float* __restrict__ C, int M, int N, int K,
                      const float* __restrict__ bias, const float* __restrict__ res) {
    extern __shared__ __align__(16) float sm[];

    const int t    = threadIdx.x;
    const int lane = t & 31;
    const int warp = t >> 5;
    const int wm   = warp & 3;
    const int wn   = warp >> 2;
    const int lr   = lane >> 2;
    const int lc   = lane & 3;
    const int bm   = blockIdx.y * 128, bn = blockIdx.x * 128;
    const int m0   = wm * 32, n0 = wn * 64;

    const int amA = t >> 2;
    const int akA = (t & 3) * 4;
    const int bkB = t >> 5;
    const int bnB = (t & 31) * 4;

    const float* Aptr = A + (size_t)(bm + amA) * K + akA;
    const float* Bptr = B + (size_t)bkB * N + bn + bnB;
    const size_t Astep64 = (size_t)64 * K;
    const size_t Bstep8  = (size_t)8 * N;

    const int aOff0 = amA * 20 + akA;
    const int aOff1 = (amA + 64) * 20 + akA;
    const int bOff0 = G_ASZ + bkB * 136 + bnB;
    const int bOff1 = G_ASZ + (bkB + 8) * 136 + bnB;

    float acc[2][8][4];
#pragma unroll
    for (int i = 0; i < 2; i++)
#pragma unroll
        for (int j = 0; j < 8; j++)
#pragma unroll
            for (int r = 0; r < 4; r++) acc[i][j][r] = 0.0f;

    const int KB = K >> 4;

#pragma unroll
    for (int s = 0; s < 2; s++) {
        float* st = sm + s * G_STG;
        const float* Ap = Aptr + s * 16;
        const float* Bp = Bptr + (size_t)s * 16 * N;
        cp16(st + aOff0, Ap);
        cp16(st + aOff1, Ap + Astep64);
        cp16(st + bOff0, Bp);
        cp16(st + bOff1, Bp + Bstep8);
        CP_COMMIT();
    }

    int rbuf = 0, wbuf = 2;
    for (int kb = 0; kb < KB; kb++) {
        if (kb + 1 < KB) CP_WAIT1(); else CP_WAIT0();
        __syncthreads();

        if (kb + 2 < KB) {
            float* st = sm + wbuf * G_STG;
            const float* Ap = Aptr + (kb + 2) * 16;
            const float* Bp = Bptr + (size_t)(kb + 2) * 16 * N;
            cp16(st + aOff0, Ap);
            cp16(st + aOff1, Ap + Astep64);
            cp16(st + bOff0, Bp);
            cp16(st + bOff1, Bp + Bstep8);
            CP_COMMIT();
        }

        const float* As_ = sm + rbuf * G_STG;
        const float* Bs_ = As_ + G_ASZ;

        // hoist ALL fragment loads (both k-substeps) before any MMA
        uint32_t af[2][2][4];
        uint32_t bf[2][8][2];
#pragma unroll
        for (int ks = 0; ks < 2; ks++) {
            const int k0 = ks * 8;
#pragma unroll
            for (int mt = 0; mt < 2; mt++) {
                int mr = m0 + mt * 16 + lr;
                af[ks][mt][0] = __float_as_uint(As_[mr * 20 + k0 + lc]);
                af[ks][mt][1] = __float_as_uint(As_[(mr + 8) * 20 + k0 + lc]);
                af[ks][mt][2] = __float_as_uint(As_[mr * 20 + k0 + lc + 4]);
                af[ks][mt][3] = __float_as_uint(As_[(mr + 8) * 20 + k0 + lc + 4]);
            }
#pragma unroll
            for (int nt = 0; nt < 8; nt++) {
                int nc = n0 + nt * 8 + lr;
                bf[ks][nt][0] = __float_as_uint(Bs_[(k0 + lc) * 136 + nc]);
                bf[ks][nt][1] = __float_as_uint(Bs_[(k0 + lc + 4) * 136 + nc]);
            }
        }
#pragma unroll
        for (int ks = 0; ks < 2; ks++)
#pragma unroll
            for (int nt = 0; nt < 8; nt++) {
                mma_tf32(acc[0][nt], af[ks][0], bf[ks][nt]);
                mma_tf32(acc[1][nt], af[ks][1], bf[ks][nt]);
            }

        rbuf = (rbuf + 1) % 3;
        wbuf = (wbuf + 1) % 3;
    }

#pragma unroll
    for (int mt = 0; mt < 2; mt++) {
#pragma unroll
        for (int half = 0; half < 2; half++) {
            int row = bm + m0 + mt * 16 + lr + half * 8;
            float* Crow = C + (size_t)row * N + bn;
            const float* Rrow = (EPI >= 2) ? (res + (size_t)row * N + bn) : nullptr;
#pragma unroll
            for (int nt = 0; nt < 8; nt++) {
                int col = n0 + nt * 8 + lc * 2;
                float2 v = make_float2(acc[mt][nt][half * 2], acc[mt][nt][half * 2 + 1]);
                if (EPI == 1 || EPI == 3) {
                    float2 bb = *(const float2*)(bias + bn + col);
                    v.x += bb.x; v.y += bb.y;
                }
                if (EPI == 1) { v.x = fmaxf(v.x, 0.f); v.y = fmaxf(v.y, 0.f); }
                if (EPI >= 2) {
                    float2 rr = *(const float2*)(Rrow + col);
                    v.x += rr.x; v.y += rr.y;
                }
                *(float2*)&Crow[col] = v;
            }
        }
    }
}

// ---------------- tensor-core flash attention, 64q x 64k tiles ----------------
// grid: (QLEN/64, BSZ, NH), 256 threads (8 warps). Dynamic smem.
// Layout (floats): Ks[64][68], Vs[64][72], Ss[64][68] (Q staged here at init),
// m/l/al[64] each.
#define AT_KS 68
#define AT_VS 72
#define AT_SS 68
#define AT_KS_OFF 0
#define AT_VS_OFF (64 * AT_KS)
#define AT_SS_OFF (AT_VS_OFF + 64 * AT_VS)
#define AT_ML_OFF (AT_SS_OFF + 64 * AT_SS)
#define AT_SMEM ((AT_ML_OFF + 192) * 4)

__global__ __launch_bounds__(256)
void attn_tc_kernel(const float* __restrict__ Q, const float* __restrict__ KV,
                    float* __restrict__ Vout) {
    extern __shared__ __align__(16) float smf[];
    float* Ks  = smf + AT_KS_OFF;
    float* Vs  = smf + AT_VS_OFF;
    float* Ss  = smf + AT_SS_OFF;
    float* m_s = smf + AT_ML_OFF;
    float* l_s = m_s + 64;
    float* al_s = m_s + 128;

    const int qb = blockIdx.x, b = blockIdx.y, hh = blockIdx.z;
    const int t = threadIdx.x, lane = t & 31, warp = t >> 5;
    const int lr = lane >> 2, lc = lane & 3;

    // QK mapping: S^T [64 kj][64 q]; warp covers kj in [kb2, kb2+32), q in [nq0, nq0+16)
    const int kb2 = (warp & 1) * 32;
    const int nq0 = (warp >> 1) * 16;
    // PV mapping: O [64 q][64 d]
    const int mq0 = (warp & 3) * 16;
    const int nd0 = (warp >> 2) * 32;
    // KV staging: thread handles rows kjA + 16s (s=0..3), cols d4A..d4A+3
    const int kjA = t >> 4;
    const int d4A = (t & 15) * 4;

    // ---- init: stage Q (tf32) into the Ss region, extract persistent fragments
    float* Qs = Ss;   // [64][65] overlay, init only
    for (int idx = t; idx < 64 * 16; idx += 256) {
        int qi = idx >> 4, d4 = (idx & 15) * 4;
        float4 v = *(const float4*)&Q[((size_t)((qb * 64 + qi) * BSZ + b)) * DMODEL
                                      + hh * DHEAD + d4];
        Qs[qi * 65 + d4 + 0] = __uint_as_float(f2tf(v.x));
        Qs[qi * 65 + d4 + 1] = __uint_as_float(f2tf(v.y));
        Qs[qi * 65 + d4 + 2] = __uint_as_float(f2tf(v.z));
        Qs[qi * 65 + d4 + 3] = __uint_as_float(f2tf(v.w));
    }
    if (t < 64) { m_s[t] = -INFINITY; l_s[t] = 0.0f; }
    __syncthreads();

    uint32_t qf[2][8][2];
#pragma unroll
    for (int nt = 0; nt < 2; nt++)
#pragma unroll
        for (int c = 0; c < 8; c++) {
            int qcol = nq0 + nt * 8 + lr;
            qf[nt][c][0] = __float_as_uint(Qs[qcol * 65 + c * 8 + lc]);
            qf[nt][c][1] = __float_as_uint(Qs[qcol * 65 + c * 8 + lc + 4]);
        }

    float oacc[4][4];
#pragma unroll
    for (int i = 0; i < 4; i++)
#pragma unroll
        for (int j = 0; j < 4; j++) oacc[i][j] = 0.0f;

    const int nTiles = 17 + qb;          // 64-key tiles; covers MLEN + qb*64 + 63
    const int lastTile = nTiles - 1;     // only the final tile needs masking

    // prologue: KV tile 0 into registers
    float4 kr[4], vr[4];
#pragma unroll
    for (int s = 0; s < 4; s++) {
        size_t ba = ((size_t)(kjA + 16 * s) * BSZ + b) * (2 * DMODEL) + hh * DHEAD + d4A;
        kr[s] = *(const float4*)&KV[ba];
        vr[s] = *(const float4*)&KV[ba + DMODEL];
    }

    for (int tile = 0; tile < nTiles; tile++) {
        const int j0 = tile * 64;
        __syncthreads();   // previous tile's readers of Ks/Vs/Ss are done

        // stage registers -> smem (tf32), float4 stores
#pragma unroll
        for (int s = 0; s < 4; s++) {
            *(float4*)&Ks[(kjA + 16 * s) * AT_KS + d4A] = tf4(kr[s]);
            *(float4*)&Vs[(kjA + 16 * s) * AT_VS + d4A] = tf4(vr[s]);
        }
        // prefetch next tile (latency hides under compute)
        if (tile + 1 < nTiles) {
#pragma unroll
            for (int s = 0; s < 4; s++) {
                size_t ba = ((size_t)(j0 + 64 + kjA + 16 * s) * BSZ + b) * (2 * DMODEL)
                            + hh * DHEAD + d4A;
                kr[s] = *(const float4*)&KV[ba];
                vr[s] = *(const float4*)&KV[ba + DMODEL];
            }
        }
        __syncthreads();

        // S^T = K @ Q^T : 2 kj-tiles x 2 q-tiles per warp
        float sacc[2][2][4];
#pragma unroll
        for (int i = 0; i < 2; i++)
#pragma unroll
            for (int j = 0; j < 2; j++)
#pragma unroll
                for (int r = 0; r < 4; r++) sacc[i][j][r] = 0.0f;
#pragma unroll
        for (int mt2 = 0; mt2 < 2; mt2++) {
#pragma unroll
            for (int c = 0; c < 8; c++) {
                uint32_t af[4];
                int kr0 = (kb2 + mt2 * 16 + lr) * AT_KS;
                af[0] = __float_as_uint(Ks[kr0 + c * 8 + lc]);
                af[1] = __float_as_uint(Ks[kr0 + 8 * AT_KS + c * 8 + lc]);
                af[2] = __float_as_uint(Ks[kr0 + c * 8 + lc + 4]);
                af[3] = __float_as_uint(Ks[kr0 + 8 * AT_KS + c * 8 + lc + 4]);
                mma_tf32(sacc[mt2][0], af, qf[0][c]);
                mma_tf32(sacc[mt2][1], af, qf[1][c]);
            }
        }
        const bool maskTile = (tile == lastTile);
#pragma unroll
        for (int mt2 = 0; mt2 < 2; mt2++)
#pragma unroll
            for (int nt = 0; nt < 2; nt++)
#pragma unroll
                for (int i = 0; i < 4; i++) {
                    int kjl = kb2 + mt2 * 16 + lr + ((i >> 1) ? 8 : 0);
                    int ql  = nq0 + nt * 8 + 2 * lc + (i & 1);
                    float v = sacc[mt2][nt][i] * 0.125f;
                    if (maskTile && (j0 + kjl > MLEN + qb * 64 + ql)) v = -INFINITY;
                    Ss[ql * AT_SS + kjl] = v;
                }
        __syncthreads();

        // online softmax over 64 keys; lane group of 4 per q row
        {
            int srow = t >> 2, sq = t & 3;
            float sv[16];
            float mx = -INFINITY;
#pragma unroll
            for (int j = 0; j < 16; j++) {
                sv[j] = Ss[srow * AT_SS + 4 * j + sq];
                mx = fmaxf(mx, sv[j]);
            }
            mx = fmaxf(mx, __shfl_xor_sync(0xffffffffu, mx, 1));
            mx = fmaxf(mx, __shfl_xor_sync(0xffffffffu, mx, 2));
            float mOld = m_s[srow];
            float mNew = fmaxf(mOld, mx);
            float al   = expf(mOld - mNew);
            float sum = 0.0f;
#pragma unroll
            for (int j = 0; j < 16; j++) {
                float p = expf(sv[j] - mNew);
                Ss[srow * AT_SS + 4 * j + sq] = __uint_as_float(f2tf(p));
                sum += p;
            }
            sum += __shfl_xor_sync(0xffffffffu, sum, 1);
            sum += __shfl_xor_sync(0xffffffffu, sum, 2);
            if (sq == 0) { m_s[srow] = mNew; l_s[srow] = l_s[srow] * al + sum; al_s[srow] = al; }
        }
        __syncthreads();

        // O += P @ V : 8 kj-chunks
        float a0 = al_s[mq0 + lr], a1 = al_s[mq0 + 8 + lr];
#pragma unroll
        for (int nt = 0; nt < 4; nt++) {
            oacc[nt][0] *= a0; oacc[nt][1] *= a0;
            oacc[nt][2] *= a1; oacc[nt][3] *= a1;
        }
#pragma unroll
        for (int c = 0; c < 8; c++) {
            uint32_t af[4];
            int pr0 = (mq0 + lr) * AT_SS;
            af[0] = __float_as_uint(Ss[pr0 + c * 8 + lc]);
            af[1] = __float_as_uint(Ss[pr0 + 8 * AT_SS + c * 8 + lc]);
            af[2] = __float_as_uint(Ss[pr0 + c * 8 + lc + 4]);
            af[3] = __float_as_uint(Ss[pr0 + 8 * AT_SS + c * 8 + lc + 4]);
#pragma unroll
            for (int nt = 0; nt < 4; nt++) {
                uint32_t bfv[2];
                bfv[0] = __float_as_uint(Vs[(c * 8 + lc) * AT_VS + nd0 + nt * 8 + lr]);
                bfv[1] = __float_as_uint(Vs[(c * 8 + lc + 4) * AT_VS + nd0 + nt * 8 + lr]);
                mma_tf32(oacc[nt], af, bfv);
            }
        }
    }

    // final normalize + store
#pragma unroll
    for (int half = 0; half < 2; half++) {
        int q = mq0 + lr + half * 8;
        float invl = 1.0f / l_s[q];
        float* orow = &Vout[((size_t)((qb * 64 + q) * BSZ + b)) * DMODEL + hh * DHEAD];
#pragma unroll
        for (int nt = 0; nt < 4; nt++) {
            float2 v = make_float2(oacc[nt][half * 2] * invl, oacc[nt][half * 2 + 1] * invl);
            *(float2*)&orow[nd0 + nt * 8 + 2 * lc] = v;
        }
    }
}

// ---------------- layernorm ---------------------------------------------------
__global__ __launch_bounds__(128)
void ln_kernel(const float* __restrict__ x, const float* __restrict__ g,
               const float* __restrict__ bparm, float* __restrict__ out) {
    const int row = blockIdx.x;
    const int t = threadIdx.x;
    float4 v = ((const float4*)(x + (size_t)row * DMODEL))[t];
    float s  = v.x + v.y + v.z + v.w;
    float s2 = fmaf(v.x, v.x, fmaf(v.y, v.y, fmaf(v.z, v.z, v.w * v.w)));
#pragma unroll
    for (int o = 16; o > 0; o >>= 1) {
        s  += __shfl_down_sync(0xffffffffu, s, o);
        s2 += __shfl_down_sync(0xffffffffu, s2, o);
    }
    __shared__ float ss[4], ss2[4];
    int w = t >> 5;
    if ((t & 31) == 0) { ss[w] = s; ss2[w] = s2; }
    __syncthreads();
    float tot  = ss[0] + ss[1] + ss[2] + ss[3];
    float tot2 = ss2[0] + ss2[1] + ss2[2] + ss2[3];
    float mu  = tot * (1.0f / DMODEL);
    float var = tot2 * (1.0f / DMODEL) - mu * mu;
    float rs  = rsqrtf(var + 1e-5f);
    float4 gg = ((const float4*)g)[t];
    float4 bb = ((const float4*)bparm)[t];
    float4 o;
    o.x = (v.x - mu) * rs * gg.x + bb.x;
    o.y = (v.y - mu) * rs * gg.y + bb.y;
    o.z = (v.z - mu) * rs * gg.z + bb.z;
    o.w = (v.w - mu) * rs * gg.w + bb.w;
    ((float4*)(out + (size_t)row * DMODEL))[t] = o;
}

// ---------------- launch ------------------------------------------------------
extern "C" void kernel_launch(void* const* d_in, const int* in_sizes, int n_in,
                              void* d_out, int out_size) {
    const int*   inp  = (const int*)d_in[0];
    const float* emb  = (const float*)d_in[1];
    const float* mems = (const float*)d_in[2];
    const float* Wq   = (const float*)d_in[3];
    const float* Wkv  = (const float*)d_in[4];
    const float* Wo   = (const float*)d_in[5];
    const float* ln1g = (const float*)d_in[6];
    const float* ln1b = (const float*)d_in[7];
    const float* W1   = (const float*)d_in[8];
    const float* b1   = (const float*)d_in[9];
    const float* W2   = (const float*)d_in[10];
    const float* b2   = (const float*)d_in[11];
    const float* ln2g = (const float*)d_in[12];
    const float* ln2b = (const float*)d_in[13];
    float* out = (float*)d_out;

    float *h, *c, *q, *kv, *vec, *ff, *tmp;
    cudaGetSymbolAddress((void**)&h,   g_h);
    cudaGetSymbolAddress((void**)&c,   g_c);
    cudaGetSymbolAddress((void**)&q,   g_q);
    cudaGetSymbolAddress((void**)&kv,  g_kv);
    cudaGetSymbolAddress((void**)&vec, g_vec);
    cudaGetSymbolAddress((void**)&ff,  g_ff);
    cudaGetSymbolAddress((void**)&tmp, g_tmp);

    cudaFuncSetAttribute(gemm_tf32_kernel<0>, cudaFuncAttributeMaxDynamicSharedMemorySize, G_SMEM);
    cudaFuncSetAttribute(gemm_tf32_kernel<1>, cudaFuncAttributeMaxDynamicSharedMemorySize, G_SMEM);
    cudaFuncSetAttribute(gemm_tf32_kernel<2>, cudaFuncAttributeMaxDynamicSharedMemorySize, G_SMEM);
    cudaFuncSetAttribute(gemm_tf32_kernel<3>, cudaFuncAttributeMaxDynamicSharedMemorySize, G_SMEM);
    cudaFuncSetAttribute(attn_tc_kernel, cudaFuncAttributeMaxDynamicSharedMemorySize, AT_SMEM);

    embed_kernel<<<(MROWS * DMODEL + 255) / 256, 256>>>(inp, emb, h);

    for (int l = 0; l < NLAYER; l++) {
        concat_kernel<<<(CROWS * DMODEL / 4 + 255) / 256, 256>>>(
            mems + (size_t)l * MLEN * BSZ * DMODEL, h, c);

        gemm_tf32_kernel<0><<<dim3(DMODEL / 128, MROWS / 128), 256, G_SMEM>>>(
            h, Wq + (size_t)l * DMODEL * DMODEL, q,
            MROWS, DMODEL, DMODEL, nullptr, nullptr);

        gemm_tf32_kernel<0><<<dim3(2 * DMODEL / 128, CROWS / 128), 256, G_SMEM>>>(
            c, Wkv + (size_t)l * DMODEL * 2 * DMODEL, kv,
            CROWS, 2 * DMODEL, DMODEL, nullptr, nullptr);

        attn_tc_kernel<<<dim3(QLEN / 64, BSZ, NH), 256, AT_SMEM>>>(q, kv, vec);

        gemm_tf32_kernel<2><<<dim3(DMODEL / 128, MROWS / 128), 256, G_SMEM>>>(
            vec, Wo + (size_t)l * DMODEL * DMODEL, tmp,
            MROWS, DMODEL, DMODEL, nullptr, h);

        ln_kernel<<<MROWS, 128>>>(tmp, ln1g + l * DMODEL, ln1b + l * DMODEL, h);

        gemm_tf32_kernel<1><<<dim3(DFF / 128, MROWS / 128), 256, G_SMEM>>>(
            h, W1 + (size_t)l * DMODEL * DFF, ff,
            MROWS, DFF, DMODEL, b1 + l * DFF, nullptr);

        gemm_tf32_kernel<3><<<dim3(DMODEL / 128, MROWS / 128), 256, G_SMEM>>>(
            ff, W2 + (size_t)l * DFF * DMODEL, tmp,
            MROWS, DMODEL, DFF, b2 + l * DMODEL, h);

        ln_kernel<<<MROWS, 128>>>(tmp, ln2g + l * DMODEL, ln2b + l * DMODEL,
                                  (l == NLAYER - 1) ? out : h);
    }
}